// round 6
// baseline (speedup 1.0000x reference)
#include <cuda_runtime.h>

#define NB    32
#define NMEL  128
#define TT    8192
#define NKEYS 88
#define NSLOT 57
#define TH    (TT/2)

// 57 distinct mel bins used by the 88 keys (validated: rel_err 0.0 R1/R3/R4/R5)
__device__ constexpr int DBIN[NSLOT] = {
   1,  2,  3,  4,  5,  6,  7,  8,  9, 10, 11, 12, 13, 14, 15, 16, 17,
  19, 20, 21, 22, 23, 25, 26, 28, 29, 31, 33, 35, 37, 39, 42,
  44, 46, 49, 51, 53, 56, 58, 60, 63,
  65, 68, 70, 72, 75, 77, 79, 82, 84, 86, 89, 91, 93, 96, 98, 101
};

// key -> distinct-slot index (non-decreasing)
__device__ constexpr int KS[NKEYS] = {
   0, 0, 0, 0, 0,
   1, 1, 1, 1, 1, 1, 1, 1, 1,
   2, 2, 2, 2, 2, 2,
   3, 3, 3, 3,
   4, 4, 4,  5, 5, 5,  6, 6, 6,
   7, 7,  8, 8,  9, 9,
  10, 11, 11, 12, 13, 14, 15, 16, 16,
  17, 18, 19, 20, 21, 22, 23, 24, 25, 26, 27, 28, 29, 30, 31, 32,
  33, 34, 35, 36, 37, 38, 39, 40, 41, 42, 43, 44, 45, 46, 47, 48,
  49, 50, 51, 52, 53, 54, 55, 56
};

// slot -> [first key, last key)
__device__ constexpr int KST[NSLOT + 1] = {
   0,  5, 14, 20, 24, 27, 30, 33, 35, 37, 39, 40, 42, 43, 44, 45, 46, 48,
  49, 50, 51, 52, 53, 54, 55, 56, 57, 58, 59, 60, 61, 62, 63, 64, 65, 66,
  67, 68, 69, 70, 71, 72, 73, 74, 75, 76, 77, 78, 79, 80, 81, 82, 83, 84,
  85, 86, 87, 88
};

__device__ __forceinline__ float2 loadw2(const float2* __restrict__ base, int bn)
{
    float2 s = __ldg(base + (size_t)bn * TH);
    if (bn < 64) { float2 a = __ldg(base + (size_t)(2 * bn) * TH); s.x += a.x; s.y += a.y; }
    if (bn < 43) { float2 a = __ldg(base + (size_t)(3 * bn) * TH); s.x += a.x; s.y += a.y; }
    return s;
}

__global__ void __launch_bounds__(128, 5)
hps_key_probs_kernel(const float* __restrict__ mel,
                     float* __restrict__ out,
                     int write_two)
{
    const int q  = blockIdx.x * 128 + threadIdx.x;   // pair index 0..131071
    const int b  = q >> 12;                          // /4096 pairs per batch
    const int tp = (q & 4095) << 1;                  // first of 2 adjacent t

    const float2* __restrict__ m2 =
        (const float2*)(mel + (size_t)b * (NMEL * TT) + tp);

    // ---- Phase 1: streaming selection of the 14th-largest of the 88-multiset
    // (log-domain: monotone exp dropped; validated rel_err 0.0).
    float tlo[16], thi[16], glo[16], ghi[16];

    // Groups 0..4: 16 keys each (keys 0..79)
    #pragma unroll
    for (int grp = 0; grp < 5; ++grp) {
        #pragma unroll
        for (int u = 0; u < 16; ++u) {
            const float2 wv = loadw2(m2, DBIN[KS[grp * 16 + u]]);
            glo[u] = wv.x; ghi[u] = wv.y;
        }
        // bitonic sort-16 descending
        #pragma unroll
        for (int kk = 2; kk <= 16; kk <<= 1) {
            #pragma unroll
            for (int j = kk >> 1; j > 0; j >>= 1) {
                #pragma unroll
                for (int i = 0; i < 16; ++i) {
                    const int l = i ^ j;
                    if (l > i) {
                        const float a0 = glo[i], c0 = glo[l];
                        const float a1 = ghi[i], c1 = ghi[l];
                        if ((i & kk) == 0) {
                            glo[i] = fmaxf(a0, c0); glo[l] = fminf(a0, c0);
                            ghi[i] = fmaxf(a1, c1); ghi[l] = fminf(a1, c1);
                        } else {
                            glo[i] = fminf(a0, c0); glo[l] = fmaxf(a0, c0);
                            ghi[i] = fminf(a1, c1); ghi[l] = fmaxf(a1, c1);
                        }
                    }
                }
            }
        }
        if (grp == 0) {
            #pragma unroll
            for (int i = 0; i < 16; ++i) { tlo[i] = glo[i]; thi[i] = ghi[i]; }
        } else {
            // merge-keep-top-16: max vs reversed g (bitonic), then full clean
            #pragma unroll
            for (int i = 0; i < 16; ++i) {
                tlo[i] = fmaxf(tlo[i], glo[15 - i]);
                thi[i] = fmaxf(thi[i], ghi[15 - i]);
            }
            #pragma unroll
            for (int j = 8; j > 0; j >>= 1) {
                #pragma unroll
                for (int i = 0; i < 16; ++i) {
                    const int l = i ^ j;
                    if (l > i) {
                        const float a0 = tlo[i], c0 = tlo[l];
                        const float a1 = thi[i], c1 = thi[l];
                        tlo[i] = fmaxf(a0, c0); tlo[l] = fminf(a0, c0);
                        thi[i] = fmaxf(a1, c1); thi[l] = fminf(a1, c1);
                    }
                }
            }
        }
    }

    // Group 5: only 8 real keys (80..87) -> bitonic sort-8, asymmetric merge,
    // then extract ONLY rank-13 (14th largest) via half-cleaner descent.
    float cutlo, cuthi;
    {
        #pragma unroll
        for (int u = 0; u < 8; ++u) {
            const float2 wv = loadw2(m2, DBIN[KS[80 + u]]);
            glo[u] = wv.x; ghi[u] = wv.y;
        }
        // bitonic sort-8 descending
        #pragma unroll
        for (int kk = 2; kk <= 8; kk <<= 1) {
            #pragma unroll
            for (int j = kk >> 1; j > 0; j >>= 1) {
                #pragma unroll
                for (int i = 0; i < 8; ++i) {
                    const int l = i ^ j;
                    if (l > i) {
                        const float a0 = glo[i], c0 = glo[l];
                        const float a1 = ghi[i], c1 = ghi[l];
                        if ((i & kk) == 0) {
                            glo[i] = fmaxf(a0, c0); glo[l] = fminf(a0, c0);
                            ghi[i] = fmaxf(a1, c1); ghi[l] = fminf(a1, c1);
                        } else {
                            glo[i] = fminf(a0, c0); glo[l] = fmaxf(a0, c0);
                            ghi[i] = fminf(a1, c1); ghi[l] = fmaxf(a1, c1);
                        }
                    }
                }
            }
        }
        // merge: positions 8..15 see g[15-i] (i=8..15 -> g index 7..0);
        // positions 0..7 would see -inf -> unchanged.
        #pragma unroll
        for (int i = 8; i < 16; ++i) {
            tlo[i] = fmaxf(tlo[i], glo[15 - i]);
            thi[i] = fmaxf(thi[i], ghi[15 - i]);
        }
        // tt is bitonic; rank 13 descent:
        //   half-clean j=8, keep mins  -> ranks 8..15 (bitonic 8)
        //   half-clean j=4, keep mins  -> ranks 12..15 (bitonic 4)
        //   half-clean j=2, keep maxes -> ranks 12..13 (pair)
        //   rank 13 = min of the pair
        float l8lo[8], l8hi[8];
        #pragma unroll
        for (int i = 0; i < 8; ++i) {
            l8lo[i] = fminf(tlo[i], tlo[i + 8]);
            l8hi[i] = fminf(thi[i], thi[i + 8]);
        }
        float l4lo[4], l4hi[4];
        #pragma unroll
        for (int i = 0; i < 4; ++i) {
            l4lo[i] = fminf(l8lo[i], l8lo[i + 4]);
            l4hi[i] = fminf(l8hi[i], l8hi[i + 4]);
        }
        float p0lo = fmaxf(l4lo[0], l4lo[2]), p1lo = fmaxf(l4lo[1], l4lo[3]);
        float p0hi = fmaxf(l4hi[0], l4hi[2]), p1hi = fmaxf(l4hi[1], l4hi[3]);
        cutlo = fminf(p0lo, p1lo);
        cuthi = fminf(p0hi, p1hi);
    }

    // ---- Phase boundary: launder the pointer so phase-2 loads cannot be
    // CSE'd with phase-1 loads (R4/R5: CSE kept 114 slot floats live -> 194
    // regs, occ 11%). Opaque register breaks address-equality proofs.
    const float2* m2b;
    asm volatile("mov.b64 %0, %1;" : "=l"(m2b) : "l"(m2) : "memory");

    float* o0 = out + (size_t)b * (NKEYS * TT) + tp;
    const size_t half = (size_t)NB * NKEYS * TT;

    // ---- Phase 2: recompute each distinct slot (bitwise-identical math,
    // loads hit L1; __ldg keeps them reorderable past the stores), compare,
    // fan out STG.64 to contiguous keys, both output copies.
    #pragma unroll
    for (int j = 0; j < NSLOT; ++j) {
        const float2 wv = loadw2(m2b, DBIN[j]);
        float2 pv;
        pv.x = (wv.x >= cutlo) ? 1.0f : 0.0f;
        pv.y = (wv.y >= cuthi) ? 1.0f : 0.0f;
        #pragma unroll
        for (int k = KST[j]; k < KST[j + 1]; ++k) {
            *(float2*)(o0 + (size_t)k * TT) = pv;
            if (write_two) *(float2*)(o0 + (size_t)k * TT + half) = pv;
        }
    }
}

extern "C" void kernel_launch(void* const* d_in, const int* in_sizes, int n_in,
                              void* d_out, int out_size)
{
    const float* mel = (const float*)d_in[0];
    float* out = (float*)d_out;
    const long long half = (long long)NB * NKEYS * TT;   // 23,068,672
    const int write_two = (out_size >= 2 * half) ? 1 : 0;

    const int pairs = NB * TT / 2;       // 131072
    hps_key_probs_kernel<<<pairs / 128, 128>>>(mel, out, write_two);
}

// round 7
// speedup vs baseline: 1.3457x; 1.3457x over previous
#include <cuda_runtime.h>

#define NB    32
#define NMEL  128
#define TT    8192
#define NKEYS 88
#define NSLOT 57

// 57 distinct mel bins used by the 88 keys (validated rel_err 0.0, R1..R6)
__device__ constexpr int DBIN[NSLOT] = {
   1,  2,  3,  4,  5,  6,  7,  8,  9, 10, 11, 12, 13, 14, 15, 16, 17,
  19, 20, 21, 22, 23, 25, 26, 28, 29, 31, 33, 35, 37, 39, 42,
  44, 46, 49, 51, 53, 56, 58, 60, 63,
  65, 68, 70, 72, 75, 77, 79, 82, 84, 86, 89, 91, 93, 96, 98, 101
};

// key -> distinct-slot index (non-decreasing)
__device__ constexpr int KS[NKEYS] = {
   0, 0, 0, 0, 0,
   1, 1, 1, 1, 1, 1, 1, 1, 1,
   2, 2, 2, 2, 2, 2,
   3, 3, 3, 3,
   4, 4, 4,  5, 5, 5,  6, 6, 6,
   7, 7,  8, 8,  9, 9,
  10, 11, 11, 12, 13, 14, 15, 16, 16,
  17, 18, 19, 20, 21, 22, 23, 24, 25, 26, 27, 28, 29, 30, 31, 32,
  33, 34, 35, 36, 37, 38, 39, 40, 41, 42, 43, 44, 45, 46, 47, 48,
  49, 50, 51, 52, 53, 54, 55, 56
};

// slot -> [first key, last key)
__device__ constexpr int KST[NSLOT + 1] = {
   0,  5, 14, 20, 24, 27, 30, 33, 35, 37, 39, 40, 42, 43, 44, 45, 46, 48,
  49, 50, 51, 52, 53, 54, 55, 56, 57, 58, 59, 60, 61, 62, 63, 64, 65, 66,
  67, 68, 69, 70, 71, 72, 73, 74, 75, 76, 77, 78, 79, 80, 81, 82, 83, 84,
  85, 86, 87, 88
};

__device__ __forceinline__ float loadw(const float* __restrict__ mb, int bn)
{
    float s = __ldg(mb + (size_t)bn * TT);
    if (bn < 64) s += __ldg(mb + (size_t)(2 * bn) * TT);
    if (bn < 43) s += __ldg(mb + (size_t)(3 * bn) * TT);
    return s;
}

__global__ void __launch_bounds__(128, 7)
hps_key_probs_kernel(const float* __restrict__ mel,
                     float* __restrict__ out,
                     int write_two)
{
    // Handoff buffer only: written once in phase 1, read once in phase 2.
    // Layout ws[slot*128 + lane] -> conflict-free, 28.5KB -> 7 blocks/SM.
    __shared__ float ws[NSLOT * 128];

    const int p = blockIdx.x * 128 + threadIdx.x;   // 0..262143
    const int b = p >> 13;
    const int t = p & (TT - 1);

    const float* __restrict__ mb = mel + (size_t)b * (NMEL * TT) + t;
    float* wcol = ws + threadIdx.x;

    float tt[16], g[16];

    // ---- Phase 1: streaming selection of the 14th-largest (log-domain).
    // Slot values come straight from gmem into registers; each slot is STS'd
    // once at its first key so phase 2 never touches gmem.
    #pragma unroll
    for (int grp = 0; grp < 5; ++grp) {
        #pragma unroll
        for (int u = 0; u < 16; ++u) {
            const int k = grp * 16 + u;
            const int s = KS[k];
            const float v = loadw(mb, DBIN[s]);   // dup addresses CSE in-group
            g[u] = v;
            if (k == KST[s]) wcol[s * 128] = v;   // store once per slot
        }
        // bitonic sort-16 descending (compile-time lanes)
        #pragma unroll
        for (int kk = 2; kk <= 16; kk <<= 1) {
            #pragma unroll
            for (int j = kk >> 1; j > 0; j >>= 1) {
                #pragma unroll
                for (int i = 0; i < 16; ++i) {
                    const int l = i ^ j;
                    if (l > i) {
                        const float a = g[i], c = g[l];
                        if ((i & kk) == 0) { g[i] = fmaxf(a, c); g[l] = fminf(a, c); }
                        else               { g[i] = fminf(a, c); g[l] = fmaxf(a, c); }
                    }
                }
            }
        }
        if (grp == 0) {
            #pragma unroll
            for (int i = 0; i < 16; ++i) tt[i] = g[i];
        } else {
            // merge-keep-top-16: max vs reversed g (bitonic) then clean
            #pragma unroll
            for (int i = 0; i < 16; ++i) tt[i] = fmaxf(tt[i], g[15 - i]);
            #pragma unroll
            for (int j = 8; j > 0; j >>= 1) {
                #pragma unroll
                for (int i = 0; i < 16; ++i) {
                    const int l = i ^ j;
                    if (l > i) {
                        const float a = tt[i], c = tt[l];
                        tt[i] = fmaxf(a, c); tt[l] = fminf(a, c);
                    }
                }
            }
        }
    }

    // Tail group: 8 keys (80..87) -> sort-8, asym merge, rank-13 extraction
    // (structure validated rel_err 0.0 in R6).
    float cut;
    {
        #pragma unroll
        for (int u = 0; u < 8; ++u) {
            const int k = 80 + u;
            const int s = KS[k];
            const float v = loadw(mb, DBIN[s]);
            g[u] = v;
            if (k == KST[s]) wcol[s * 128] = v;
        }
        #pragma unroll
        for (int kk = 2; kk <= 8; kk <<= 1) {
            #pragma unroll
            for (int j = kk >> 1; j > 0; j >>= 1) {
                #pragma unroll
                for (int i = 0; i < 8; ++i) {
                    const int l = i ^ j;
                    if (l > i) {
                        const float a = g[i], c = g[l];
                        if ((i & kk) == 0) { g[i] = fmaxf(a, c); g[l] = fminf(a, c); }
                        else               { g[i] = fminf(a, c); g[l] = fmaxf(a, c); }
                    }
                }
            }
        }
        // positions 8..15 absorb g[7..0]; 0..7 unchanged (pad = -inf)
        #pragma unroll
        for (int i = 8; i < 16; ++i) tt[i] = fmaxf(tt[i], g[15 - i]);
        // tt bitonic; descend to rank 13 (14th largest):
        float l8[8];
        #pragma unroll
        for (int i = 0; i < 8; ++i) l8[i] = fminf(tt[i], tt[i + 8]);
        float l4[4];
        #pragma unroll
        for (int i = 0; i < 4; ++i) l4[i] = fminf(l8[i], l8[i + 4]);
        const float p0 = fmaxf(l4[0], l4[2]);
        const float p1 = fmaxf(l4[1], l4[3]);
        cut = fminf(p0, p1);
    }

    // ---- Phase boundary: launder the smem pointer so the compiler cannot
    // forward the STS'd values (would re-create the 194-reg live set of R4).
    const float* wr;
    asm volatile("mov.b64 %0, %1;" : "=l"(wr) : "l"((const float*)wcol) : "memory");

    float* o0 = out + (size_t)b * (NKEYS * TT) + t;
    const size_t half = (size_t)NB * NKEYS * TT;

    // ---- Phase 2: 57 LDS + compare, fan out to contiguous keys, both copies.
    #pragma unroll
    for (int j = 0; j < NSLOT; ++j) {
        const float pv = (wr[j * 128] >= cut) ? 1.0f : 0.0f;
        #pragma unroll
        for (int k = KST[j]; k < KST[j + 1]; ++k) {
            o0[(size_t)k * TT] = pv;
            if (write_two) o0[(size_t)k * TT + half] = pv;
        }
    }
}

extern "C" void kernel_launch(void* const* d_in, const int* in_sizes, int n_in,
                              void* d_out, int out_size)
{
    const float* mel = (const float*)d_in[0];
    float* out = (float*)d_out;
    const long long half = (long long)NB * NKEYS * TT;   // 23,068,672
    const int write_two = (out_size >= 2 * half) ? 1 : 0;

    const int points = NB * TT;          // 262144
    hps_key_probs_kernel<<<points / 128, 128>>>(mel, out, write_two);
}

// round 8
// speedup vs baseline: 1.4406x; 1.0705x over previous
#include <cuda_runtime.h>

#define NB    32
#define NMEL  128
#define TT    8192
#define NKEYS 88
#define NSLOT 57

// 57 distinct mel bins used by the 88 keys (validated rel_err 0.0, R1..R7)
__device__ constexpr int DBIN[NSLOT] = {
   1,  2,  3,  4,  5,  6,  7,  8,  9, 10, 11, 12, 13, 14, 15, 16, 17,
  19, 20, 21, 22, 23, 25, 26, 28, 29, 31, 33, 35, 37, 39, 42,
  44, 46, 49, 51, 53, 56, 58, 60, 63,
  65, 68, 70, 72, 75, 77, 79, 82, 84, 86, 89, 91, 93, 96, 98, 101
};

// key -> distinct-slot index (non-decreasing)
__device__ constexpr int KS[NKEYS] = {
   0, 0, 0, 0, 0,
   1, 1, 1, 1, 1, 1, 1, 1, 1,
   2, 2, 2, 2, 2, 2,
   3, 3, 3, 3,
   4, 4, 4,  5, 5, 5,  6, 6, 6,
   7, 7,  8, 8,  9, 9,
  10, 11, 11, 12, 13, 14, 15, 16, 16,
  17, 18, 19, 20, 21, 22, 23, 24, 25, 26, 27, 28, 29, 30, 31, 32,
  33, 34, 35, 36, 37, 38, 39, 40, 41, 42, 43, 44, 45, 46, 47, 48,
  49, 50, 51, 52, 53, 54, 55, 56
};

// slot -> [first key, last key)
__device__ constexpr int KST[NSLOT + 1] = {
   0,  5, 14, 20, 24, 27, 30, 33, 35, 37, 39, 40, 42, 43, 44, 45, 46, 48,
  49, 50, 51, 52, 53, 54, 55, 56, 57, 58, 59, 60, 61, 62, 63, 64, 65, 66,
  67, 68, 69, 70, 71, 72, 73, 74, 75, 76, 77, 78, 79, 80, 81, 82, 83, 84,
  85, 86, 87, 88
};

__global__ void __launch_bounds__(128, 5)
hps_key_probs_kernel(const float* __restrict__ mel,
                     float* __restrict__ out,
                     int write_two)
{
    const int p = blockIdx.x * 128 + threadIdx.x;   // 0..262143
    const int b = p >> 13;
    const int t = p & (TT - 1);

    const float* __restrict__ mb = mel + (size_t)b * (NMEL * TT) + t;

    // ---- Load all 57 distinct slot values into registers (log-domain HPS:
    // m[bin] (+ m[2bin]) (+ m[3bin]); exp dropped by monotonicity, validated).
    // __ldcs: single-use data, evict-first so L2 stays available for the
    // outgoing write stream.
    float w[NSLOT];
    #pragma unroll
    for (int j = 0; j < NSLOT; ++j) {
        const int bn = DBIN[j];
        float s = __ldcs(mb + (size_t)bn * TT);
        if (bn < 64) s += __ldcs(mb + (size_t)(2 * bn) * TT);
        if (bn < 43) s += __ldcs(mb + (size_t)(3 * bn) * TT);
        w[j] = s;
    }

    float tt[16], g[16];

    // ---- Streaming selection of the 14th-largest of the 88-multiset.
    // Groups 0..4: 16 keys each.
    #pragma unroll
    for (int grp = 0; grp < 5; ++grp) {
        #pragma unroll
        for (int u = 0; u < 16; ++u) g[u] = w[KS[grp * 16 + u]];
        // bitonic sort-16 descending (compile-time lanes)
        #pragma unroll
        for (int kk = 2; kk <= 16; kk <<= 1) {
            #pragma unroll
            for (int j = kk >> 1; j > 0; j >>= 1) {
                #pragma unroll
                for (int i = 0; i < 16; ++i) {
                    const int l = i ^ j;
                    if (l > i) {
                        const float a = g[i], c = g[l];
                        if ((i & kk) == 0) { g[i] = fmaxf(a, c); g[l] = fminf(a, c); }
                        else               { g[i] = fminf(a, c); g[l] = fmaxf(a, c); }
                    }
                }
            }
        }
        if (grp == 0) {
            #pragma unroll
            for (int i = 0; i < 16; ++i) tt[i] = g[i];
        } else {
            // merge-keep-top-16: max vs reversed g (bitonic) then clean
            #pragma unroll
            for (int i = 0; i < 16; ++i) tt[i] = fmaxf(tt[i], g[15 - i]);
            #pragma unroll
            for (int j = 8; j > 0; j >>= 1) {
                #pragma unroll
                for (int i = 0; i < 16; ++i) {
                    const int l = i ^ j;
                    if (l > i) {
                        const float a = tt[i], c = tt[l];
                        tt[i] = fmaxf(a, c); tt[l] = fminf(a, c);
                    }
                }
            }
        }
    }

    // Tail group: 8 keys (80..87) -> sort-8, asym merge, rank-13 extraction
    // (validated rel_err 0.0 in R6/R7).
    float cut;
    {
        #pragma unroll
        for (int u = 0; u < 8; ++u) g[u] = w[KS[80 + u]];
        #pragma unroll
        for (int kk = 2; kk <= 8; kk <<= 1) {
            #pragma unroll
            for (int j = kk >> 1; j > 0; j >>= 1) {
                #pragma unroll
                for (int i = 0; i < 8; ++i) {
                    const int l = i ^ j;
                    if (l > i) {
                        const float a = g[i], c = g[l];
                        if ((i & kk) == 0) { g[i] = fmaxf(a, c); g[l] = fminf(a, c); }
                        else               { g[i] = fminf(a, c); g[l] = fmaxf(a, c); }
                    }
                }
            }
        }
        // positions 8..15 absorb g[7..0]; 0..7 unchanged (pad = -inf)
        #pragma unroll
        for (int i = 8; i < 16; ++i) tt[i] = fmaxf(tt[i], g[15 - i]);
        // tt bitonic; descend to rank 13 (14th largest)
        float l8[8];
        #pragma unroll
        for (int i = 0; i < 8; ++i) l8[i] = fminf(tt[i], tt[i + 8]);
        float l4[4];
        #pragma unroll
        for (int i = 0; i < 4; ++i) l4[i] = fminf(l8[i], l8[i + 4]);
        const float p0 = fmaxf(l4[0], l4[2]);
        const float p1 = fmaxf(l4[1], l4[3]);
        cut = fminf(p0, p1);
    }

    float* o0 = out + (size_t)b * (NKEYS * TT) + t;
    const size_t half = (size_t)NB * NKEYS * TT;

    // ---- Output: one compare per slot, fan out to contiguous keys, both
    // copies. __stcs: evict-first dirty lines stream to DRAM promptly.
    #pragma unroll
    for (int j = 0; j < NSLOT; ++j) {
        const float pv = (w[j] >= cut) ? 1.0f : 0.0f;
        #pragma unroll
        for (int k = KST[j]; k < KST[j + 1]; ++k) {
            __stcs(o0 + (size_t)k * TT, pv);
            if (write_two) __stcs(o0 + (size_t)k * TT + half, pv);
        }
    }
}

extern "C" void kernel_launch(void* const* d_in, const int* in_sizes, int n_in,
                              void* d_out, int out_size)
{
    const float* mel = (const float*)d_in[0];
    float* out = (float*)d_out;
    const long long half = (long long)NB * NKEYS * TT;   // 23,068,672
    const int write_two = (out_size >= 2 * half) ? 1 : 0;

    const int points = NB * TT;          // 262144
    hps_key_probs_kernel<<<points / 128, 128>>>(mel, out, write_two);
}